// round 1
// baseline (speedup 1.0000x reference)
#include <cuda_runtime.h>
#include <math.h>

#define HH 512
#define WW 512
#define BB 8
#define KK 16
#define HW (HH*WW)
#define NB 16384
#define GRID_LS 1023.0f   // linspace(0,1,1024) step denominator

struct Accum {
    unsigned int cnt[BB*KK];
    float sx[BB*KK], sy[BB*KK], ss[BB*KK], ss2[BB*KK];
    float cx[BB*KK], cy[BB*KK], sexp[BB*KK];
    float seedloss[BB], instloss[BB], varloss[BB], presents[BB];
    int is64;
};
__device__ Accum g_acc;
__device__ float2        g_emb[BB*HW];
__device__ float         g_seed[BB*HW];
__device__ unsigned char g_mk[BB*HW];

// ---------------------------------------------------------------------------
// Kernel A: detect whether instances/labels are int64 (JAX x64 on) or int32.
// int64 little-endian: high words (odd uint32 indices) are all zero for 0..16.
// int32 real data: odd indices hold actual values, many nonzero.
// ---------------------------------------------------------------------------
__global__ void detect_kernel(const unsigned int* inst_raw) {
    if (threadIdx.x == 0) {
        int any = 0;
        #pragma unroll 4
        for (int i = 1; i < 4096; i += 2) any |= (inst_raw[i] != 0u);
        g_acc.is64 = any ? 0 : 1;
    }
}

// ---------------------------------------------------------------------------
// Kernel B: per-pixel prep + per-(b,k) first-moment reductions.
// grid: (HW/1024, BB), block: 256 threads, 4 pixels/thread.
// ---------------------------------------------------------------------------
__global__ void prep_kernel(const float* __restrict__ pred,
                            const void* __restrict__ instp,
                            const void* __restrict__ labp) {
    __shared__ float s_sx[KK], s_sy[KK], s_ss[KK], s_ss2[KK];
    __shared__ unsigned int s_cnt[KK];
    __shared__ float s_seedbg;

    const int tid = threadIdx.x;
    if (tid < KK) { s_sx[tid]=0.f; s_sy[tid]=0.f; s_ss[tid]=0.f; s_ss2[tid]=0.f; s_cnt[tid]=0u; }
    if (tid == 0) s_seedbg = 0.f;
    __syncthreads();

    const int b = blockIdx.y;
    const int is64 = g_acc.is64;
    const float* pb = pred + (size_t)b * 4 * HW;
    const long long base = (long long)b * HW;

    float seedbg_local = 0.f;

    #pragma unroll
    for (int j = 0; j < 4; j++) {
        int i = blockIdx.x * 1024 + j * 256 + tid;
        int col = i & (WW - 1);
        int row = i >> 9;
        float x = (float)col * (1.0f / GRID_LS);
        float y = (float)row * (1.0f / GRID_LS);

        float p0 = pb[i];
        float p1 = pb[HW + i];
        float p2 = pb[2 * HW + i];
        float p3 = pb[3 * HW + i];

        float ex = tanhf(p0) + x;
        float ey = tanhf(p1) + y;
        float sd = 1.0f / (1.0f + expf(-p3));

        long long off = base + i;
        g_emb[off]  = make_float2(ex, ey);
        g_seed[off] = sd;

        int inst, lab;
        if (is64) {
            inst = (int)((const long long*)instp)[off];
            lab  = (int)((const long long*)labp)[off];
        } else {
            inst = ((const int*)instp)[off];
            lab  = ((const int*)labp)[off];
        }

        unsigned char m = (lab == 1 && inst >= 1 && inst <= KK) ? (unsigned char)inst : 0;
        g_mk[off] = m;

        if (lab == 0) seedbg_local += sd * sd;
        if (m) {
            int kk = m - 1;
            atomicAdd(&s_cnt[kk], 1u);
            atomicAdd(&s_sx[kk], x);
            atomicAdd(&s_sy[kk], y);
            atomicAdd(&s_ss[kk], p2);
            atomicAdd(&s_ss2[kk], p2 * p2);
        }
    }

    // warp-reduce seedbg before smem atomic
    #pragma unroll
    for (int o = 16; o; o >>= 1) seedbg_local += __shfl_down_sync(0xffffffffu, seedbg_local, o);
    if ((tid & 31) == 0) atomicAdd(&s_seedbg, seedbg_local);

    __syncthreads();
    if (tid < KK && s_cnt[tid]) {
        int idx = b * KK + tid;
        atomicAdd(&g_acc.cnt[idx], s_cnt[tid]);
        atomicAdd(&g_acc.sx[idx],  s_sx[tid]);
        atomicAdd(&g_acc.sy[idx],  s_sy[tid]);
        atomicAdd(&g_acc.ss[idx],  s_ss[tid]);
        atomicAdd(&g_acc.ss2[idx], s_ss2[tid]);
    }
    if (tid == 0) atomicAdd(&g_acc.seedloss[b], s_seedbg);
}

// ---------------------------------------------------------------------------
// Kernel C: per-(b,k) parameters + var loss. 1 block, 128 threads.
// ---------------------------------------------------------------------------
__global__ void params_kernel() {
    int t = threadIdx.x;
    if (t < BB * KK) {
        int b = t >> 4;
        float cnt  = (float)g_acc.cnt[t];
        float safe = fmaxf(cnt, 1.0f);
        float mean = g_acc.ss[t] / safe;
        g_acc.cx[t]   = g_acc.sx[t] / safe;
        g_acc.cy[t]   = g_acc.sy[t] / safe;
        g_acc.sexp[t] = expf(10.0f * mean);
        if (cnt > 0.f) {
            float var = (g_acc.ss2[t] - cnt * mean * mean) / safe; // N_SIGMA=1
            atomicAdd(&g_acc.varloss[b], var);
            atomicAdd(&g_acc.presents[b], 1.0f);
        }
    }
}

// ---------------------------------------------------------------------------
// Kernel D: Lovász hinge via histogram + integral of Jaccard.
// One CTA per (b,k). 1024 threads. 128KB dynamic smem: hn[NB] u32, hg[NB] u32.
// Also accumulates the masked seed-dist term.
// ---------------------------------------------------------------------------
__global__ void __launch_bounds__(1024, 1) lovasz_kernel() {
    extern __shared__ unsigned int sh[];
    unsigned int* hn = sh;
    unsigned int* hg = sh + NB;
    __shared__ float warpN[32], warpG[32];

    const int bk = blockIdx.x;
    const int b  = bk >> 4;
    const int k  = bk & (KK - 1);
    const int tid = threadIdx.x;
    const int lane = tid & 31;
    const int wid  = tid >> 5;

    for (int i = tid; i < 2 * NB; i += 1024) sh[i] = 0u;

    const float G  = (float)g_acc.cnt[bk];
    const float cx = g_acc.cx[bk];
    const float cy = g_acc.cy[bk];
    const float s  = g_acc.sexp[bk];
    __syncthreads();

    const float2* __restrict__ emb  = g_emb  + (size_t)b * HW;
    const float*  __restrict__ seedp= g_seed + (size_t)b * HW;
    const unsigned char* __restrict__ mk = g_mk + (size_t)b * HW;
    const unsigned char kid = (unsigned char)(k + 1);
    const float SCALE = (float)NB / 2.0f;

    float seedacc = 0.f;

    for (int i = tid; i < HW; i += 1024) {
        float2 e = emb[i];
        unsigned char m = mk[i];
        float dx = e.x - cx;
        float dy = e.y - cy;
        float diff2 = fmaf(dx, dx, dy * dy);
        float d = __expf(-s * diff2);
        bool ism = (m == kid);
        float err = ism ? (2.0f - 2.0f * d) : (2.0f * d);
        int bin = (int)(err * SCALE);
        bin = min(bin, NB - 1);

        // warp-aggregated smem atomic for n-histogram
        unsigned msk = __match_any_sync(0xffffffffu, bin);
        int ldr = __ffs(msk) - 1;
        if (lane == ldr) atomicAdd(&hn[bin], (unsigned)__popc(msk));

        if (ism) {
            atomicAdd(&hg[bin], 1u);
            float sdv = seedp[i] - d;
            seedacc += sdv * sdv;
        }
    }
    __syncthreads();

    // Integrate J(t) from the top bin downward (reverse suffix scan).
    float lossJ = 0.f;
    float carN = 0.f, carG = 0.f;

    #pragma unroll 1
    for (int c = 0; c < NB / 1024; c++) {
        int idx = NB - 1 - (c * 1024 + tid);
        float n = (float)hn[idx];
        float g = (float)hg[idx];

        float sn = n, sg = g;
        #pragma unroll
        for (int o = 1; o < 32; o <<= 1) {
            float tn = __shfl_up_sync(0xffffffffu, sn, o);
            float tg = __shfl_up_sync(0xffffffffu, sg, o);
            if (lane >= o) { sn += tn; sg += tg; }
        }
        if (lane == 31) { warpN[wid] = sn; warpG[wid] = sg; }
        __syncthreads();
        if (wid == 0) {
            float wn = warpN[lane], wg = warpG[lane];
            #pragma unroll
            for (int o = 1; o < 32; o <<= 1) {
                float tn = __shfl_up_sync(0xffffffffu, wn, o);
                float tg = __shfl_up_sync(0xffffffffu, wg, o);
                if (lane >= o) { wn += tn; wg += tg; }
            }
            warpN[lane] = wn; warpG[lane] = wg;
        }
        __syncthreads();
        float offN = wid ? warpN[wid - 1] : 0.f;
        float offG = wid ? warpG[wid - 1] : 0.f;
        float totN = warpN[31];
        float totG = warpG[31];
        __syncthreads();   // protect warpN/warpG before next chunk writes

        float cumN = carN + offN + sn;
        float cumG = carG + offG + sg;
        carN += totN;
        carG += totG;

        // midpoint rule within the bin
        float nEff = cumN - 0.5f * n;
        float gEff = cumG - 0.5f * g;
        float inter = G - gEff;
        float uni   = G + nEff - gEff;
        float J = 1.0f - inter / uni;   // valid when G > 0
        lossJ += J;
    }

    // block-reduce lossJ and seedacc
    #pragma unroll
    for (int o = 16; o; o >>= 1) {
        lossJ   += __shfl_down_sync(0xffffffffu, lossJ, o);
        seedacc += __shfl_down_sync(0xffffffffu, seedacc, o);
    }
    if (lane == 0) { warpN[wid] = lossJ; warpG[wid] = seedacc; }
    __syncthreads();
    if (tid == 0) {
        float L = 0.f, S = 0.f;
        #pragma unroll
        for (int i = 0; i < 32; i++) { L += warpN[i]; S += warpG[i]; }
        if (G > 0.f) atomicAdd(&g_acc.instloss[b], L * (2.0f / NB));
        atomicAdd(&g_acc.seedloss[b], S);
    }
}

// ---------------------------------------------------------------------------
// Kernel E: finalize.
// ---------------------------------------------------------------------------
__global__ void finalize_kernel(float* out) {
    if (threadIdx.x == 0) {
        float tot = 0.f;
        #pragma unroll
        for (int b = 0; b < BB; b++) {
            float obj = fmaxf(g_acc.presents[b], 1.0f);
            tot += g_acc.instloss[b] / obj
                 + 10.0f * g_acc.varloss[b] / obj
                 + g_acc.seedloss[b] / (float)HW;
        }
        out[0] = tot / (float)BB;
    }
}

// ---------------------------------------------------------------------------
extern "C" void kernel_launch(void* const* d_in, const int* in_sizes, int n_in,
                              void* d_out, int out_size) {
    (void)in_sizes; (void)n_in; (void)out_size;
    const float* pred = (const float*)d_in[0];
    const void*  instp = d_in[1];
    const void*  labp  = d_in[2];

    void* accp = nullptr;
    cudaGetSymbolAddress(&accp, g_acc);
    cudaMemsetAsync(accp, 0, sizeof(Accum), 0);

    detect_kernel<<<1, 32>>>((const unsigned int*)instp);

    dim3 g1(HW / 1024, BB);
    prep_kernel<<<g1, 256>>>(pred, instp, labp);

    params_kernel<<<1, 128>>>();

    cudaFuncSetAttribute(lovasz_kernel,
                         cudaFuncAttributeMaxDynamicSharedMemorySize, 2 * NB * 4);
    lovasz_kernel<<<BB * KK, 1024, 2 * NB * 4>>>();

    finalize_kernel<<<1, 32>>>((float*)d_out);
}

// round 2
// speedup vs baseline: 1.2406x; 1.2406x over previous
#include <cuda_runtime.h>
#include <math.h>

#define HH 512
#define WW 512
#define BB 8
#define KK 16
#define HW (HH*WW)
#define BK (BB*KK)
#define NB 4096
#define SPLIT 4
#define MSPLIT 4
#define INV_GRID (1.0f/1023.0f)
#define LOG2E 1.4426950408889634f

struct Accum {
    float cnt[BK], scol[BK], srow[BK], ss[BK], ss2[BK];
    float cx[BK], cy[BK], s2[BK];
    float seedloss[BB], instloss[BB], varloss[BB], presents[BB];
    int is64;
};
__device__ Accum g_acc;
__device__ float2        g_emb[BB*HW];
__device__ float         g_seed[BB*HW];
__device__ unsigned char g_mk[BB*HW];
__device__ unsigned int  g_hist[BK][2][NB];

__device__ __forceinline__ float tanh_fast(float x){
    float y; asm("tanh.approx.f32 %0, %1;" : "=f"(y) : "f"(x)); return y;
}

// ---------------------------------------------------------------------------
// Detect int64 vs int32 indices (warp-parallel).
// ---------------------------------------------------------------------------
__global__ void detect_kernel(const unsigned int* __restrict__ r){
    unsigned any = 0;
    for (int i = threadIdx.x; i < 2048; i += 32) any |= r[2*i + 1];
    unsigned bal = __ballot_sync(0xffffffffu, any != 0u);
    if (threadIdx.x == 0) g_acc.is64 = bal ? 0 : 1;
}

// ---------------------------------------------------------------------------
// Prep: pure streaming. emb=tanh+xy, seed=sigmoid, mask byte, bg seed loss.
// grid (HW/2048, BB), 512 threads, 4 px/thread, vectorized.
// ---------------------------------------------------------------------------
__global__ void __launch_bounds__(512) prep_kernel(const float* __restrict__ pred,
                                                   const void* __restrict__ instp,
                                                   const void* __restrict__ labp) {
    __shared__ float s_bg[16];
    const int tid = threadIdx.x;
    const int b = blockIdx.y;
    const int i4 = blockIdx.x * 2048 + tid * 4;
    const int is64 = g_acc.is64;
    const float* pb = pred + (size_t)b * 4 * HW;
    const size_t off = (size_t)b * HW + i4;

    float4 p0 = *(const float4*)(pb + i4);
    float4 p1 = *(const float4*)(pb + HW + i4);
    float4 p3 = *(const float4*)(pb + 3*HW + i4);

    int inst[4], lab[4];
    if (is64) {
        const int4* ip = (const int4*)instp;
        const int4* lp = (const int4*)labp;
        size_t q = off >> 1;
        int4 a = ip[q],   c = ip[q+1];
        int4 d0 = lp[q],  d1 = lp[q+1];
        inst[0]=a.x; inst[1]=a.z; inst[2]=c.x; inst[3]=c.z;
        lab[0]=d0.x; lab[1]=d0.z; lab[2]=d1.x; lab[3]=d1.z;
    } else {
        int4 a  = ((const int4*)instp)[off>>2];
        int4 d0 = ((const int4*)labp)[off>>2];
        inst[0]=a.x; inst[1]=a.y; inst[2]=a.z; inst[3]=a.w;
        lab[0]=d0.x; lab[1]=d0.y; lab[2]=d0.z; lab[3]=d0.w;
    }

    float y  = (float)(i4 >> 9) * INV_GRID;
    float xb = (float)(i4 & (WW-1)) * INV_GRID;

    const float* p0a = (const float*)&p0;
    const float* p1a = (const float*)&p1;
    const float* p3a = (const float*)&p3;
    float ex[4], ey[4], sd[4];
    #pragma unroll
    for (int j = 0; j < 4; j++) {
        ex[j] = tanh_fast(p0a[j]) + (xb + j*INV_GRID);
        ey[j] = tanh_fast(p1a[j]) + y;
        sd[j] = fmaf(tanh_fast(0.5f*p3a[j]), 0.5f, 0.5f);   // sigmoid
    }
    ((float4*)(g_emb+off))[0] = make_float4(ex[0],ey[0],ex[1],ey[1]);
    ((float4*)(g_emb+off))[1] = make_float4(ex[2],ey[2],ex[3],ey[3]);
    *(float4*)(g_seed+off)    = make_float4(sd[0],sd[1],sd[2],sd[3]);

    unsigned mk4 = 0;
    float bg = 0.f;
    #pragma unroll
    for (int j = 0; j < 4; j++) {
        unsigned m = (lab[j]==1 && inst[j]>=1 && inst[j]<=KK) ? (unsigned)inst[j] : 0u;
        mk4 |= m << (8*j);
        if (lab[j]==0) bg += sd[j]*sd[j];
    }
    *(unsigned*)(g_mk+off) = mk4;

    #pragma unroll
    for (int o = 16; o; o >>= 1) bg += __shfl_down_sync(0xffffffffu, bg, o);
    if ((tid & 31) == 0) s_bg[tid>>5] = bg;
    __syncthreads();
    if (tid == 0) {
        float t = 0.f;
        #pragma unroll
        for (int w = 0; w < 16; w++) t += s_bg[w];
        atomicAdd(&g_acc.seedloss[b], t);
    }
}

// ---------------------------------------------------------------------------
// Moments: per (b,k), register accumulation, zero per-pixel atomics.
// grid (MSPLIT, BK), 512 threads.
// ---------------------------------------------------------------------------
__global__ void __launch_bounds__(512) moments_kernel(const float* __restrict__ pred){
    __shared__ float s_red[16*5];
    const int bk = blockIdx.y;
    const int b = bk >> 4;
    const unsigned kid4 = ((unsigned)(bk & 15) + 1u) * 0x01010101u;
    const int tid = threadIdx.x;
    const float* p2 = pred + (size_t)b*4*HW + 2*HW;
    const unsigned char* mk = g_mk + (size_t)b*HW;
    const int pbase = blockIdx.x * (HW / MSPLIT);

    float cnt=0.f, scol=0.f, srow=0.f, ss=0.f, ss2=0.f;

    #pragma unroll 4
    for (int g = 0; g < (HW/MSPLIT)/(512*4); g++){
        int i4 = pbase + (g*512 + tid)*4;
        unsigned m4 = *(const unsigned*)(mk + i4);
        unsigned eq = __vcmpeq4(m4, kid4);
        if (eq){
            float row = (float)(i4 >> 9);
            int colb = i4 & (WW-1);
            #pragma unroll
            for (int j = 0; j < 4; j++){
                if ((eq >> (8*j)) & 1u){
                    float v = p2[i4+j];
                    cnt += 1.f; scol += (float)(colb+j); srow += row;
                    ss += v; ss2 = fmaf(v, v, ss2);
                }
            }
        }
    }
    int lane = tid & 31, wid = tid >> 5;
    #pragma unroll
    for (int o = 16; o; o >>= 1){
        cnt += __shfl_down_sync(0xffffffffu,cnt ,o);
        scol+= __shfl_down_sync(0xffffffffu,scol,o);
        srow+= __shfl_down_sync(0xffffffffu,srow,o);
        ss  += __shfl_down_sync(0xffffffffu,ss  ,o);
        ss2 += __shfl_down_sync(0xffffffffu,ss2 ,o);
    }
    if (lane == 0){
        s_red[wid*5+0]=cnt; s_red[wid*5+1]=scol; s_red[wid*5+2]=srow;
        s_red[wid*5+3]=ss;  s_red[wid*5+4]=ss2;
    }
    __syncthreads();
    if (tid == 0){
        float a0=0,a1=0,a2=0,a3=0,a4=0;
        #pragma unroll
        for (int w=0;w<16;w++){a0+=s_red[w*5];a1+=s_red[w*5+1];a2+=s_red[w*5+2];a3+=s_red[w*5+3];a4+=s_red[w*5+4];}
        if (a0 > 0.f){
            atomicAdd(&g_acc.cnt[bk], a0); atomicAdd(&g_acc.scol[bk], a1);
            atomicAdd(&g_acc.srow[bk], a2); atomicAdd(&g_acc.ss[bk],  a3);
            atomicAdd(&g_acc.ss2[bk],  a4);
        }
    }
}

// ---------------------------------------------------------------------------
// Params: per-(b,k) center / exp(10*mean) / var loss.
// ---------------------------------------------------------------------------
__global__ void params_kernel(){
    int t = threadIdx.x;
    if (t < BK){
        int b = t >> 4;
        float cnt = g_acc.cnt[t];
        float safe = fmaxf(cnt, 1.f);
        float mean = g_acc.ss[t] / safe;
        g_acc.cx[t] = (g_acc.scol[t] / safe) * INV_GRID;
        g_acc.cy[t] = (g_acc.srow[t] / safe) * INV_GRID;
        g_acc.s2[t] = expf(10.f * mean) * LOG2E;
        if (cnt > 0.f){
            float var = (g_acc.ss2[t] - cnt*mean*mean) / safe;
            atomicAdd(&g_acc.varloss[b], var);
            atomicAdd(&g_acc.presents[b], 1.f);
        }
    }
}

// ---------------------------------------------------------------------------
// Lovasz histogram: SPLIT CTAs per (b,k), smem hist, merge to global.
// bin(nonmask) = floor(d*NB) = floor(exp2(12 - s2*t2)); bin(mask) = floor(NB - d*NB)
// ---------------------------------------------------------------------------
__global__ void __launch_bounds__(512,3) lovasz_kernel(){
    __shared__ unsigned hn[NB];
    __shared__ unsigned hg[NB];
    __shared__ float s_red[16];
    const int bs = blockIdx.x;
    const int bk = bs >> 2;             // SPLIT=4
    const int half = bs & 3;
    const int b = bk >> 4;
    const int tid = threadIdx.x;
    const int lane = tid & 31;

    for (int i = tid; i < NB; i += 512){ hn[i]=0u; hg[i]=0u; }
    const float cx = g_acc.cx[bk];
    const float cy = g_acc.cy[bk];
    const float s2 = g_acc.s2[bk];
    const unsigned kid4 = ((unsigned)(bk & 15) + 1u) * 0x01010101u;
    __syncthreads();

    const float2* emb = g_emb + (size_t)b*HW;
    const float* seedp = g_seed + (size_t)b*HW;
    const unsigned char* mk = g_mk + (size_t)b*HW;
    const int pbase = half * (HW/SPLIT);
    float seedacc = 0.f;

    #pragma unroll 1
    for (int g = 0; g < (HW/SPLIT)/(512*4); g++){   // 32 iterations
        int i4 = pbase + (g*512 + tid)*4;
        float4 e01 = ((const float4*)(emb+i4))[0];
        float4 e23 = ((const float4*)(emb+i4))[1];
        unsigned m4 = *(const unsigned*)(mk + i4);
        unsigned eq = __vcmpeq4(m4, kid4);
        float exs[4] = {e01.x, e01.z, e23.x, e23.z};
        float eys[4] = {e01.y, e01.w, e23.y, e23.w};
        #pragma unroll
        for (int j = 0; j < 4; j++){
            float dx = exs[j]-cx, dy = eys[j]-cy;
            float t2 = fmaf(dx, dx, dy*dy);
            float v = exp2f(fmaf(t2, -s2, 12.0f));     // = d*NB in (0,4096]
            bool ism = (eq >> (8*j)) & 1u;
            float binf = ism ? (4096.0f - v) : v;
            int bin = min((int)binf, NB-1);
            unsigned mm = __match_any_sync(0xffffffffu, bin);
            if ((__ffs(mm)-1) == lane) atomicAdd(&hn[bin], (unsigned)__popc(mm));
            if (ism){
                atomicAdd(&hg[bin], 1u);
                float sv = seedp[i4+j] - v*(1.0f/4096.0f);
                seedacc = fmaf(sv, sv, seedacc);
            }
        }
    }
    __syncthreads();
    for (int i = tid; i < NB; i += 512){
        unsigned n = hn[i]; if (n)  atomicAdd(&g_hist[bk][0][i], n);
        unsigned gg = hg[i]; if (gg) atomicAdd(&g_hist[bk][1][i], gg);
    }
    #pragma unroll
    for (int o = 16; o; o >>= 1) seedacc += __shfl_down_sync(0xffffffffu, seedacc, o);
    if (lane == 0) s_red[tid>>5] = seedacc;
    __syncthreads();
    if (tid == 0){
        float t = 0.f;
        #pragma unroll
        for (int w = 0; w < 16; w++) t += s_red[w];
        atomicAdd(&g_acc.seedloss[b], t);
    }
}

// ---------------------------------------------------------------------------
// Scan: suffix-cumsum + midpoint integration of Jaccard. 1 CTA per (b,k).
// ---------------------------------------------------------------------------
__global__ void __launch_bounds__(1024) scan_kernel(){
    __shared__ float warpN[32], warpG[32];
    const int bk = blockIdx.x;
    const int b = bk >> 4;
    const int tid = threadIdx.x, lane = tid & 31, wid = tid >> 5;
    const float G = g_acc.cnt[bk];
    const unsigned* __restrict__ hn = g_hist[bk][0];
    const unsigned* __restrict__ hg = g_hist[bk][1];

    float lossJ = 0.f, carN = 0.f, carG = 0.f;

    #pragma unroll 1
    for (int c = 0; c < NB/1024; c++){
        int idx = NB - 1 - (c*1024 + tid);
        float n = (float)hn[idx];
        float g = (float)hg[idx];

        float sn = n, sg = g;
        #pragma unroll
        for (int o = 1; o < 32; o <<= 1){
            float tn = __shfl_up_sync(0xffffffffu, sn, o);
            float tg = __shfl_up_sync(0xffffffffu, sg, o);
            if (lane >= o){ sn += tn; sg += tg; }
        }
        if (lane == 31){ warpN[wid] = sn; warpG[wid] = sg; }
        __syncthreads();
        if (wid == 0){
            float wn = warpN[lane], wg = warpG[lane];
            #pragma unroll
            for (int o = 1; o < 32; o <<= 1){
                float tn = __shfl_up_sync(0xffffffffu, wn, o);
                float tg = __shfl_up_sync(0xffffffffu, wg, o);
                if (lane >= o){ wn += tn; wg += tg; }
            }
            warpN[lane] = wn; warpG[lane] = wg;
        }
        __syncthreads();
        float offN = wid ? warpN[wid-1] : 0.f;
        float offG = wid ? warpG[wid-1] : 0.f;
        float totN = warpN[31];
        float totG = warpG[31];
        __syncthreads();

        float cumN = carN + offN + sn;
        float cumG = carG + offG + sg;
        carN += totN;
        carG += totG;

        float nEff = cumN - 0.5f*n;
        float gEff = cumG - 0.5f*g;
        float inter = G - gEff;
        float uni   = G + nEff - gEff;
        lossJ += 1.0f - inter/uni;
    }

    #pragma unroll
    for (int o = 16; o; o >>= 1) lossJ += __shfl_down_sync(0xffffffffu, lossJ, o);
    if (lane == 0) warpN[wid] = lossJ;
    __syncthreads();
    if (tid == 0 && G > 0.f){
        float L = 0.f;
        #pragma unroll
        for (int i = 0; i < 32; i++) L += warpN[i];
        atomicAdd(&g_acc.instloss[b], L * (2.0f/NB));
    }
}

// ---------------------------------------------------------------------------
__global__ void finalize_kernel(float* out){
    if (threadIdx.x == 0){
        float tot = 0.f;
        #pragma unroll
        for (int b = 0; b < BB; b++){
            float obj = fmaxf(g_acc.presents[b], 1.0f);
            tot += g_acc.instloss[b] / obj
                 + 10.0f * g_acc.varloss[b] / obj
                 + g_acc.seedloss[b] / (float)HW;
        }
        out[0] = tot / (float)BB;
    }
}

// ---------------------------------------------------------------------------
extern "C" void kernel_launch(void* const* d_in, const int* in_sizes, int n_in,
                              void* d_out, int out_size) {
    (void)in_sizes; (void)n_in; (void)out_size;
    const float* pred = (const float*)d_in[0];

    void* accp = nullptr; void* histp = nullptr;
    cudaGetSymbolAddress(&accp, g_acc);
    cudaGetSymbolAddress(&histp, g_hist);
    cudaMemsetAsync(accp, 0, sizeof(Accum), 0);
    cudaMemsetAsync(histp, 0, sizeof(unsigned)*BK*2*NB, 0);

    detect_kernel<<<1, 32>>>((const unsigned int*)d_in[1]);

    dim3 gp(HW/2048, BB);
    prep_kernel<<<gp, 512>>>(pred, d_in[1], d_in[2]);

    dim3 gm(MSPLIT, BK);
    moments_kernel<<<gm, 512>>>(pred);

    params_kernel<<<1, 128>>>();

    lovasz_kernel<<<BK*SPLIT, 512>>>();

    scan_kernel<<<BK, 1024>>>();

    finalize_kernel<<<1, 32>>>((float*)d_out);
}

// round 3
// speedup vs baseline: 1.3751x; 1.1084x over previous
#include <cuda_runtime.h>
#include <math.h>

#define HH 512
#define WW 512
#define BB 8
#define KK 16
#define HW (HH*WW)
#define BK (BB*KK)
#define NBU 4096                 // u-bins (uniform in s*diff^2)
#define NB  4096                 // err-bins (scan space, err coord = d*4096)
#define UMAX 12.0f
#define SPLIT 8
#define MSPLIT 4
#define INV_GRID (1.0f/1023.0f)
#define LOG2E 1.4426950408889634f

struct Accum {
    float cnt[BK], scol[BK], srow[BK], ss[BK], ss2[BK];
    float cx[BK], cy[BK], sE[BK];
    float seedloss[BB], instloss[BB], varloss[BB], presents[BB];
    int is64;
};
__device__ Accum g_acc;
__device__ float2        g_emb[BB*HW];
__device__ float         g_seed[BB*HW];
__device__ unsigned char g_mk[BB*HW];
__device__ unsigned int  g_uhist[BK][NBU];   // nonmask, u-binned
__device__ unsigned int  g_mhist[BK][NB];    // mask, exact err-binned

__device__ __forceinline__ float tanh_fast(float x){
    float y; asm("tanh.approx.f32 %0, %1;" : "=f"(y) : "f"(x)); return y;
}

// ---------------------------------------------------------------------------
__global__ void detect_kernel(const unsigned int* __restrict__ r){
    unsigned any = 0;
    for (int i = threadIdx.x; i < 2048; i += 32) any |= r[2*i + 1];
    unsigned bal = __ballot_sync(0xffffffffu, any != 0u);
    if (threadIdx.x == 0) g_acc.is64 = bal ? 0 : 1;
}

// ---------------------------------------------------------------------------
// Prep: emb = tanh + xy, seed = sigmoid, mask byte, bg seed loss.
// ---------------------------------------------------------------------------
__global__ void __launch_bounds__(512) prep_kernel(const float* __restrict__ pred,
                                                   const void* __restrict__ instp,
                                                   const void* __restrict__ labp) {
    __shared__ float s_bg[16];
    const int tid = threadIdx.x;
    const int b = blockIdx.y;
    const int i4 = blockIdx.x * 2048 + tid * 4;
    const int is64 = g_acc.is64;
    const float* pb = pred + (size_t)b * 4 * HW;
    const size_t off = (size_t)b * HW + i4;

    float4 p0 = *(const float4*)(pb + i4);
    float4 p1 = *(const float4*)(pb + HW + i4);
    float4 p3 = *(const float4*)(pb + 3*HW + i4);

    int inst[4], lab[4];
    if (is64) {
        const int4* ip = (const int4*)instp;
        const int4* lp = (const int4*)labp;
        size_t q = off >> 1;
        int4 a = ip[q],   c = ip[q+1];
        int4 d0 = lp[q],  d1 = lp[q+1];
        inst[0]=a.x; inst[1]=a.z; inst[2]=c.x; inst[3]=c.z;
        lab[0]=d0.x; lab[1]=d0.z; lab[2]=d1.x; lab[3]=d1.z;
    } else {
        int4 a  = ((const int4*)instp)[off>>2];
        int4 d0 = ((const int4*)labp)[off>>2];
        inst[0]=a.x; inst[1]=a.y; inst[2]=a.z; inst[3]=a.w;
        lab[0]=d0.x; lab[1]=d0.y; lab[2]=d0.z; lab[3]=d0.w;
    }

    float y  = (float)(i4 >> 9) * INV_GRID;
    float xb = (float)(i4 & (WW-1)) * INV_GRID;

    const float* p0a = (const float*)&p0;
    const float* p1a = (const float*)&p1;
    const float* p3a = (const float*)&p3;
    float ex[4], ey[4], sd[4];
    #pragma unroll
    for (int j = 0; j < 4; j++) {
        ex[j] = tanh_fast(p0a[j]) + (xb + j*INV_GRID);
        ey[j] = tanh_fast(p1a[j]) + y;
        sd[j] = fmaf(tanh_fast(0.5f*p3a[j]), 0.5f, 0.5f);
    }
    ((float4*)(g_emb+off))[0] = make_float4(ex[0],ey[0],ex[1],ey[1]);
    ((float4*)(g_emb+off))[1] = make_float4(ex[2],ey[2],ex[3],ey[3]);
    *(float4*)(g_seed+off)    = make_float4(sd[0],sd[1],sd[2],sd[3]);

    unsigned mk4 = 0;
    float bg = 0.f;
    #pragma unroll
    for (int j = 0; j < 4; j++) {
        unsigned m = (lab[j]==1 && inst[j]>=1 && inst[j]<=KK) ? (unsigned)inst[j] : 0u;
        mk4 |= m << (8*j);
        if (lab[j]==0) bg += sd[j]*sd[j];
    }
    *(unsigned*)(g_mk+off) = mk4;

    #pragma unroll
    for (int o = 16; o; o >>= 1) bg += __shfl_down_sync(0xffffffffu, bg, o);
    if ((tid & 31) == 0) s_bg[tid>>5] = bg;
    __syncthreads();
    if (tid == 0) {
        float t = 0.f;
        #pragma unroll
        for (int w = 0; w < 16; w++) t += s_bg[w];
        atomicAdd(&g_acc.seedloss[b], t);
    }
}

// ---------------------------------------------------------------------------
// Moments: per (b,k), register accumulation.
// ---------------------------------------------------------------------------
__global__ void __launch_bounds__(512) moments_kernel(const float* __restrict__ pred){
    __shared__ float s_red[16*5];
    const int bk = blockIdx.y;
    const int b = bk >> 4;
    const unsigned kid4 = ((unsigned)(bk & 15) + 1u) * 0x01010101u;
    const int tid = threadIdx.x;
    const float* p2 = pred + (size_t)b*4*HW + 2*HW;
    const unsigned char* mk = g_mk + (size_t)b*HW;
    const int pbase = blockIdx.x * (HW / MSPLIT);

    float cnt=0.f, scol=0.f, srow=0.f, ss=0.f, ss2=0.f;

    #pragma unroll 4
    for (int g = 0; g < (HW/MSPLIT)/(512*4); g++){
        int i4 = pbase + (g*512 + tid)*4;
        unsigned m4 = *(const unsigned*)(mk + i4);
        unsigned eq = __vcmpeq4(m4, kid4);
        if (eq){
            float row = (float)(i4 >> 9);
            int colb = i4 & (WW-1);
            #pragma unroll
            for (int j = 0; j < 4; j++){
                if ((eq >> (8*j)) & 1u){
                    float v = p2[i4+j];
                    cnt += 1.f; scol += (float)(colb+j); srow += row;
                    ss += v; ss2 = fmaf(v, v, ss2);
                }
            }
        }
    }
    int lane = tid & 31, wid = tid >> 5;
    #pragma unroll
    for (int o = 16; o; o >>= 1){
        cnt += __shfl_down_sync(0xffffffffu,cnt ,o);
        scol+= __shfl_down_sync(0xffffffffu,scol,o);
        srow+= __shfl_down_sync(0xffffffffu,srow,o);
        ss  += __shfl_down_sync(0xffffffffu,ss  ,o);
        ss2 += __shfl_down_sync(0xffffffffu,ss2 ,o);
    }
    if (lane == 0){
        s_red[wid*5+0]=cnt; s_red[wid*5+1]=scol; s_red[wid*5+2]=srow;
        s_red[wid*5+3]=ss;  s_red[wid*5+4]=ss2;
    }
    __syncthreads();
    if (tid == 0){
        float a0=0,a1=0,a2=0,a3=0,a4=0;
        #pragma unroll
        for (int w=0;w<16;w++){a0+=s_red[w*5];a1+=s_red[w*5+1];a2+=s_red[w*5+2];a3+=s_red[w*5+3];a4+=s_red[w*5+4];}
        if (a0 > 0.f){
            atomicAdd(&g_acc.cnt[bk], a0); atomicAdd(&g_acc.scol[bk], a1);
            atomicAdd(&g_acc.srow[bk], a2); atomicAdd(&g_acc.ss[bk],  a3);
            atomicAdd(&g_acc.ss2[bk],  a4);
        }
    }
}

// ---------------------------------------------------------------------------
__global__ void params_kernel(){
    int t = threadIdx.x;
    if (t < BK){
        int b = t >> 4;
        float cnt = g_acc.cnt[t];
        float safe = fmaxf(cnt, 1.f);
        float mean = g_acc.ss[t] / safe;
        g_acc.cx[t] = (g_acc.scol[t] / safe) * INV_GRID;
        g_acc.cy[t] = (g_acc.srow[t] / safe) * INV_GRID;
        g_acc.sE[t] = expf(10.f * mean);       // plain exp(10*mean)
        if (cnt > 0.f){
            float var = (g_acc.ss2[t] - cnt*mean*mean) / safe;
            atomicAdd(&g_acc.varloss[b], var);
            atomicAdd(&g_acc.presents[b], 1.f);
        }
    }
}

// ---------------------------------------------------------------------------
// Hist: nonmask -> u-bins (NO exp); mask -> exact err-bins (exp also feeds
// the seed term). SPLIT CTAs per (b,k).
// ---------------------------------------------------------------------------
__global__ void __launch_bounds__(512,3) lovasz_hist_kernel(){
    __shared__ unsigned hu[NBU];   // nonmask u-hist
    __shared__ unsigned hm[NB];    // mask err-hist (exact)
    __shared__ float s_red[16];
    const int bs = blockIdx.x;
    const int bk = bs / SPLIT;
    const int part = bs % SPLIT;
    const int b = bk >> 4;
    const int tid = threadIdx.x;
    const int lane = tid & 31;

    for (int i = tid; i < NBU; i += 512) hu[i] = 0u;
    for (int i = tid; i < NB;  i += 512) hm[i] = 0u;

    const float cx = g_acc.cx[bk];
    const float cy = g_acc.cy[bk];
    const float sE = g_acc.sE[bk];
    const float S  = sE * ((float)NBU / UMAX);   // bin = floor(t2*S)
    const float KS = -sE * LOG2E;                // d = exp2f(t2*KS)
    const unsigned kid4 = ((unsigned)(bk & 15) + 1u) * 0x01010101u;
    __syncthreads();

    const float2* __restrict__ emb  = g_emb  + (size_t)b*HW;
    const float*  __restrict__ seedp= g_seed + (size_t)b*HW;
    const unsigned char* __restrict__ mk = g_mk + (size_t)b*HW;
    const int pbase = part * (HW/SPLIT);
    float seedacc = 0.f;

    #pragma unroll 1
    for (int g = 0; g < (HW/SPLIT)/(512*4); g++){   // 16 iterations
        int i4 = pbase + (g*512 + tid)*4;
        float4 e01 = ((const float4*)(emb+i4))[0];
        float4 e23 = ((const float4*)(emb+i4))[1];
        unsigned m4 = *(const unsigned*)(mk + i4);
        unsigned eq = __vcmpeq4(m4, kid4);
        float exs[4] = {e01.x, e01.z, e23.x, e23.z};
        float eys[4] = {e01.y, e01.w, e23.y, e23.w};
        #pragma unroll
        for (int j = 0; j < 4; j++){
            float dx = exs[j]-cx, dy = eys[j]-cy;
            float t2 = fmaf(dx, dx, dy*dy);
            int bin = __float2int_rd(t2 * S);
            bin = min(max(bin, 0), NBU-1);
            bool ism = (eq >> (8*j)) & 1u;
            unsigned bm = __ballot_sync(0xffffffffu, ism);
            unsigned mm = __match_any_sync(0xffffffffu, bin) & ~bm;
            if (!ism){
                if (lane == __ffs(mm)-1)
                    atomicAdd(&hu[bin], (unsigned)__popc(mm));
            } else {
                float d = exp2f(t2 * KS);
                float sv = seedp[i4+j] - d;
                seedacc = fmaf(sv, sv, seedacc);
                int eb = (NB-1) - min(__float2int_rd(d * (float)NB), NB-1);
                atomicAdd(&hm[eb], 1u);
            }
        }
    }
    __syncthreads();
    for (int i = tid; i < NBU; i += 512){
        unsigned n = hu[i]; if (n) atomicAdd(&g_uhist[bk][i], n);
    }
    for (int i = tid; i < NB; i += 512){
        unsigned n = hm[i]; if (n) atomicAdd(&g_mhist[bk][i], n);
    }
    #pragma unroll
    for (int o = 16; o; o >>= 1) seedacc += __shfl_down_sync(0xffffffffu, seedacc, o);
    if (lane == 0) s_red[tid>>5] = seedacc;
    __syncthreads();
    if (tid == 0){
        float t = 0.f;
        #pragma unroll
        for (int w = 0; w < 16; w++) t += s_red[w];
        atomicAdd(&g_acc.seedloss[b], t);
    }
}

// ---------------------------------------------------------------------------
// Scan: (1) remap u-hist -> float err-hist with proportional spreading
//       (4096 exps per instance, trivially cheap); (2) suffix scan + midpoint
//       Jaccard integration. 1 CTA per (b,k), 1024 threads.
// err coordinate p = d*NB (nonmask err bin = floor(p); mask bin = NB-1-floor(p)).
// ---------------------------------------------------------------------------
__global__ void __launch_bounds__(1024) scan_kernel(){
    __shared__ float fn[NB];
    __shared__ float warpN[32], warpG[32];
    const int bk = blockIdx.x;
    const int b = bk >> 4;
    const int tid = threadIdx.x, lane = tid & 31, wid = tid >> 5;
    const float G = g_acc.cnt[bk];
    const float KD = (UMAX / (float)NBU) * LOG2E;   // d(i) = exp2(-i*KD)

    for (int i = tid; i < NB; i += 1024) fn[i] = 0.f;
    __syncthreads();

    // remap with proportional spreading over covered err-bins
    for (int i = tid; i < NBU; i += 1024){
        unsigned c = g_uhist[bk][i];
        if (!c) continue;
        float phi = (float)NB * exp2f(-(float)i     * KD);
        float plo = (float)NB * exp2f(-(float)(i+1) * KD);
        phi = fminf(phi, (float)NB - 0.001f);
        plo = fminf(plo, phi);
        float span = phi - plo;
        float fc = (float)c;
        int b1 = (int)phi;
        if (span < 1e-6f){
            atomicAdd(&fn[b1], fc);
        } else {
            int b0 = (int)plo;
            float w = fc / span;
            if (b0 == b1){
                atomicAdd(&fn[b0], fc);
            } else {
                atomicAdd(&fn[b0], w * ((float)(b0+1) - plo));
                for (int bb = b0+1; bb < b1; bb++) atomicAdd(&fn[bb], w);
                atomicAdd(&fn[b1], w * (phi - (float)b1));
            }
        }
    }
    __syncthreads();

    const unsigned* __restrict__ hg = g_mhist[bk];
    float lossJ = 0.f, carN = 0.f, carG = 0.f;

    #pragma unroll 1
    for (int c = 0; c < NB/1024; c++){
        int idx = NB - 1 - (c*1024 + tid);
        float n = fn[idx];
        float g = (float)hg[idx];

        float sn = n, sg = g;
        #pragma unroll
        for (int o = 1; o < 32; o <<= 1){
            float tn = __shfl_up_sync(0xffffffffu, sn, o);
            float tg = __shfl_up_sync(0xffffffffu, sg, o);
            if (lane >= o){ sn += tn; sg += tg; }
        }
        if (lane == 31){ warpN[wid] = sn; warpG[wid] = sg; }
        __syncthreads();
        if (wid == 0){
            float wn = warpN[lane], wg = warpG[lane];
            #pragma unroll
            for (int o = 1; o < 32; o <<= 1){
                float tn = __shfl_up_sync(0xffffffffu, wn, o);
                float tg = __shfl_up_sync(0xffffffffu, wg, o);
                if (lane >= o){ wn += tn; wg += tg; }
            }
            warpN[lane] = wn; warpG[lane] = wg;
        }
        __syncthreads();
        float offN = wid ? warpN[wid-1] : 0.f;
        float offG = wid ? warpG[wid-1] : 0.f;
        float totN = warpN[31];
        float totG = warpG[31];
        __syncthreads();

        float cumN = carN + offN + sn;
        float cumG = carG + offG + sg;
        carN += totN;
        carG += totG;

        float nEff = cumN - 0.5f*n;
        float gEff = cumG - 0.5f*g;
        float inter = G - gEff;
        float uni   = G + nEff - gEff;
        lossJ += 1.0f - inter/uni;
    }

    #pragma unroll
    for (int o = 16; o; o >>= 1) lossJ += __shfl_down_sync(0xffffffffu, lossJ, o);
    if (lane == 0) warpN[wid] = lossJ;
    __syncthreads();
    if (tid == 0 && G > 0.f){
        float L = 0.f;
        #pragma unroll
        for (int i = 0; i < 32; i++) L += warpN[i];
        atomicAdd(&g_acc.instloss[b], L * (2.0f/NB));
    }
}

// ---------------------------------------------------------------------------
__global__ void finalize_kernel(float* out){
    if (threadIdx.x == 0){
        float tot = 0.f;
        #pragma unroll
        for (int b = 0; b < BB; b++){
            float obj = fmaxf(g_acc.presents[b], 1.0f);
            tot += g_acc.instloss[b] / obj
                 + 10.0f * g_acc.varloss[b] / obj
                 + g_acc.seedloss[b] / (float)HW;
        }
        out[0] = tot / (float)BB;
    }
}

// ---------------------------------------------------------------------------
extern "C" void kernel_launch(void* const* d_in, const int* in_sizes, int n_in,
                              void* d_out, int out_size) {
    (void)in_sizes; (void)n_in; (void)out_size;
    const float* pred = (const float*)d_in[0];

    void *accp=nullptr, *uhp=nullptr, *mhp=nullptr;
    cudaGetSymbolAddress(&accp, g_acc);
    cudaGetSymbolAddress(&uhp,  g_uhist);
    cudaGetSymbolAddress(&mhp,  g_mhist);
    cudaMemsetAsync(accp, 0, sizeof(Accum), 0);
    cudaMemsetAsync(uhp,  0, sizeof(unsigned)*BK*NBU, 0);
    cudaMemsetAsync(mhp,  0, sizeof(unsigned)*BK*NB, 0);

    detect_kernel<<<1, 32>>>((const unsigned int*)d_in[1]);

    dim3 gp(HW/2048, BB);
    prep_kernel<<<gp, 512>>>(pred, d_in[1], d_in[2]);

    dim3 gm(MSPLIT, BK);
    moments_kernel<<<gm, 512>>>(pred);

    params_kernel<<<1, 128>>>();

    lovasz_hist_kernel<<<BK*SPLIT, 512>>>();

    scan_kernel<<<BK, 1024>>>();

    finalize_kernel<<<1, 32>>>((float*)d_out);
}

// round 4
// speedup vs baseline: 3.4377x; 2.5000x over previous
#include <cuda_runtime.h>
#include <math.h>

#define HH 512
#define WW 512
#define BB 8
#define KK 16
#define HW (HH*WW)
#define BK (BB*KK)
#define NBU 8192                 // u-bins (uniform in s*diff^2)
#define NB  4096                 // err-bins (scan space, err coord = d*4096)
#define UMAX 12.0f
#define SPLIT 8
#define MSPLIT 4
#define INV_GRID (1.0f/1023.0f)
#define LOG2E 1.4426950408889634f

struct Accum {
    float cnt[BK], scol[BK], srow[BK], ss[BK], ss2[BK];
    float seedloss[BB], instloss[BB], varloss[BB], presents[BB];
    int is64;
};
__device__ Accum g_acc;
__device__ float2        g_emb[BB*HW];
__device__ float         g_seed[BB*HW];
__device__ unsigned char g_mk[BB*HW];
__device__ unsigned int  g_uhist[BK][NBU];   // nonmask, u-binned
__device__ unsigned int  g_mhist[BK][NB];    // mask, exact err-binned

__device__ __forceinline__ float tanh_fast(float x){
    float y; asm("tanh.approx.f32 %0, %1;" : "=f"(y) : "f"(x)); return y;
}

// ---------------------------------------------------------------------------
__global__ void detect_kernel(const unsigned int* __restrict__ r){
    unsigned any = 0;
    for (int i = threadIdx.x; i < 2048; i += 32) any |= r[2*i + 1];
    unsigned bal = __ballot_sync(0xffffffffu, any != 0u);
    if (threadIdx.x == 0) g_acc.is64 = bal ? 0 : 1;
}

// ---------------------------------------------------------------------------
// Prep: emb = tanh + xy, seed = sigmoid, mask byte, bg seed loss.
// ---------------------------------------------------------------------------
__global__ void __launch_bounds__(512) prep_kernel(const float* __restrict__ pred,
                                                   const void* __restrict__ instp,
                                                   const void* __restrict__ labp) {
    __shared__ float s_bg[16];
    const int tid = threadIdx.x;
    const int b = blockIdx.y;
    const int i4 = blockIdx.x * 2048 + tid * 4;
    const int is64 = g_acc.is64;
    const float* pb = pred + (size_t)b * 4 * HW;
    const size_t off = (size_t)b * HW + i4;

    float4 p0 = *(const float4*)(pb + i4);
    float4 p1 = *(const float4*)(pb + HW + i4);
    float4 p3 = *(const float4*)(pb + 3*HW + i4);

    int inst[4], lab[4];
    if (is64) {
        const int4* ip = (const int4*)instp;
        const int4* lp = (const int4*)labp;
        size_t q = off >> 1;
        int4 a = ip[q],   c = ip[q+1];
        int4 d0 = lp[q],  d1 = lp[q+1];
        inst[0]=a.x; inst[1]=a.z; inst[2]=c.x; inst[3]=c.z;
        lab[0]=d0.x; lab[1]=d0.z; lab[2]=d1.x; lab[3]=d1.z;
    } else {
        int4 a  = ((const int4*)instp)[off>>2];
        int4 d0 = ((const int4*)labp)[off>>2];
        inst[0]=a.x; inst[1]=a.y; inst[2]=a.z; inst[3]=a.w;
        lab[0]=d0.x; lab[1]=d0.y; lab[2]=d0.z; lab[3]=d0.w;
    }

    float y  = (float)(i4 >> 9) * INV_GRID;
    float xb = (float)(i4 & (WW-1)) * INV_GRID;

    const float* p0a = (const float*)&p0;
    const float* p1a = (const float*)&p1;
    const float* p3a = (const float*)&p3;
    float ex[4], ey[4], sd[4];
    #pragma unroll
    for (int j = 0; j < 4; j++) {
        ex[j] = tanh_fast(p0a[j]) + (xb + j*INV_GRID);
        ey[j] = tanh_fast(p1a[j]) + y;
        sd[j] = fmaf(tanh_fast(0.5f*p3a[j]), 0.5f, 0.5f);
    }
    ((float4*)(g_emb+off))[0] = make_float4(ex[0],ey[0],ex[1],ey[1]);
    ((float4*)(g_emb+off))[1] = make_float4(ex[2],ey[2],ex[3],ey[3]);
    *(float4*)(g_seed+off)    = make_float4(sd[0],sd[1],sd[2],sd[3]);

    unsigned mk4 = 0;
    float bg = 0.f;
    #pragma unroll
    for (int j = 0; j < 4; j++) {
        unsigned m = (lab[j]==1 && inst[j]>=1 && inst[j]<=KK) ? (unsigned)inst[j] : 0u;
        mk4 |= m << (8*j);
        if (lab[j]==0) bg += sd[j]*sd[j];
    }
    *(unsigned*)(g_mk+off) = mk4;

    #pragma unroll
    for (int o = 16; o; o >>= 1) bg += __shfl_down_sync(0xffffffffu, bg, o);
    if ((tid & 31) == 0) s_bg[tid>>5] = bg;
    __syncthreads();
    if (tid == 0) {
        float t = 0.f;
        #pragma unroll
        for (int w = 0; w < 16; w++) t += s_bg[w];
        atomicAdd(&g_acc.seedloss[b], t);
    }
}

// ---------------------------------------------------------------------------
// Moments: per (b,k), register accumulation, 16 px/thread skip-fast.
// ---------------------------------------------------------------------------
__global__ void __launch_bounds__(512) moments_kernel(const float* __restrict__ pred){
    __shared__ float s_red[16*5];
    const int bk = blockIdx.y;
    const int b = bk >> 4;
    const unsigned kid4 = ((unsigned)(bk & 15) + 1u) * 0x01010101u;
    const int tid = threadIdx.x;
    const float* p2 = pred + (size_t)b*4*HW + 2*HW;
    const unsigned char* mk = g_mk + (size_t)b*HW;
    const int pbase = blockIdx.x * (HW / MSPLIT);

    float cnt=0.f, scol=0.f, srow=0.f, ss=0.f, ss2=0.f;

    #pragma unroll
    for (int g = 0; g < (HW/MSPLIT)/(512*16); g++){   // 8 iterations
        int i16 = pbase + (g*512 + tid)*16;
        uint4 m = *(const uint4*)(mk + i16);
        unsigned e[4];
        e[0] = __vcmpeq4(m.x, kid4); e[1] = __vcmpeq4(m.y, kid4);
        e[2] = __vcmpeq4(m.z, kid4); e[3] = __vcmpeq4(m.w, kid4);
        if (e[0]|e[1]|e[2]|e[3]){
            float row = (float)(i16 >> 9);
            int colb = i16 & (WW-1);
            #pragma unroll
            for (int q = 0; q < 4; q++){
                if (!e[q]) continue;
                #pragma unroll
                for (int j = 0; j < 4; j++){
                    if ((e[q] >> (8*j)) & 1u){
                        int px = q*4 + j;
                        float v = p2[i16+px];
                        cnt += 1.f; scol += (float)(colb+px); srow += row;
                        ss += v; ss2 = fmaf(v, v, ss2);
                    }
                }
            }
        }
    }
    int lane = tid & 31, wid = tid >> 5;
    #pragma unroll
    for (int o = 16; o; o >>= 1){
        cnt += __shfl_down_sync(0xffffffffu,cnt ,o);
        scol+= __shfl_down_sync(0xffffffffu,scol,o);
        srow+= __shfl_down_sync(0xffffffffu,srow,o);
        ss  += __shfl_down_sync(0xffffffffu,ss  ,o);
        ss2 += __shfl_down_sync(0xffffffffu,ss2 ,o);
    }
    if (lane == 0){
        s_red[wid*5+0]=cnt; s_red[wid*5+1]=scol; s_red[wid*5+2]=srow;
        s_red[wid*5+3]=ss;  s_red[wid*5+4]=ss2;
    }
    __syncthreads();
    if (tid == 0){
        float a0=0,a1=0,a2=0,a3=0,a4=0;
        #pragma unroll
        for (int w=0;w<16;w++){a0+=s_red[w*5];a1+=s_red[w*5+1];a2+=s_red[w*5+2];a3+=s_red[w*5+3];a4+=s_red[w*5+4];}
        if (a0 > 0.f){
            atomicAdd(&g_acc.cnt[bk], a0); atomicAdd(&g_acc.scol[bk], a1);
            atomicAdd(&g_acc.srow[bk], a2); atomicAdd(&g_acc.ss[bk],  a3);
            atomicAdd(&g_acc.ss2[bk],  a4);
        }
    }
}

// ---------------------------------------------------------------------------
// Hist: nonmask -> u-bins via PLAIN smem atomics (bins are iid-scattered by
// tanh noise -> ~2 collisions/warp; aggregation machinery costs more than it
// saves). Mask (~3%) -> exact err-bins via rare global atomics + seed term.
// Params (cx,cy,S) derived inline from raw moments.
// ---------------------------------------------------------------------------
__global__ void __launch_bounds__(512,3) lovasz_hist_kernel(){
    __shared__ unsigned hu[NBU];
    __shared__ float s_red[16];
    const int bs = blockIdx.x;
    const int bk = bs / SPLIT;
    const int part = bs % SPLIT;
    const int b = bk >> 4;
    const int tid = threadIdx.x;

    for (int i = tid; i < NBU; i += 512) hu[i] = 0u;

    const float cntk = g_acc.cnt[bk];
    const float safe = fmaxf(cntk, 1.f);
    const float mean = g_acc.ss[bk] / safe;
    const float cx = (g_acc.scol[bk] / safe) * INV_GRID;
    const float cy = (g_acc.srow[bk] / safe) * INV_GRID;
    const float sE = expf(10.f * mean);
    const float S  = sE * ((float)NBU / UMAX);   // u-bin = floor(t2*S)
    const float KS = -sE * LOG2E;                // d = exp2f(t2*KS)
    const unsigned kid4 = ((unsigned)(bk & 15) + 1u) * 0x01010101u;
    __syncthreads();

    const float2* __restrict__ emb  = g_emb  + (size_t)b*HW;
    const float*  __restrict__ seedp= g_seed + (size_t)b*HW;
    const unsigned char* __restrict__ mk = g_mk + (size_t)b*HW;
    unsigned* __restrict__ mh = g_mhist[bk];
    const int pbase = part * (HW/SPLIT);
    float seedacc = 0.f;

    #pragma unroll 1
    for (int g = 0; g < (HW/SPLIT)/(512*4); g++){   // 16 iterations
        int i4 = pbase + (g*512 + tid)*4;
        float4 e01 = ((const float4*)(emb+i4))[0];
        float4 e23 = ((const float4*)(emb+i4))[1];
        unsigned m4 = *(const unsigned*)(mk + i4);
        unsigned eq = __vcmpeq4(m4, kid4);
        float exs[4] = {e01.x, e01.z, e23.x, e23.z};
        float eys[4] = {e01.y, e01.w, e23.y, e23.w};
        #pragma unroll
        for (int j = 0; j < 4; j++){
            float dx = exs[j]-cx, dy = eys[j]-cy;
            float t2 = fmaf(dx, dx, dy*dy);
            if (!((eq >> (8*j)) & 1u)){
                int bin = min(__float2int_rd(t2 * S), NBU-1);
                atomicAdd(&hu[bin], 1u);
            } else {
                float d = exp2f(t2 * KS);
                float sv = seedp[i4+j] - d;
                seedacc = fmaf(sv, sv, seedacc);
                int eb = (NB-1) - min(__float2int_rd(d * (float)NB), NB-1);
                atomicAdd(&mh[eb], 1u);
            }
        }
    }
    __syncthreads();
    for (int i = tid; i < NBU; i += 512){
        unsigned n = hu[i]; if (n) atomicAdd(&g_uhist[bk][i], n);
    }
    #pragma unroll
    for (int o = 16; o; o >>= 1) seedacc += __shfl_down_sync(0xffffffffu, seedacc, o);
    if ((tid & 31) == 0) s_red[tid>>5] = seedacc;
    __syncthreads();
    if (tid == 0){
        float t = 0.f;
        #pragma unroll
        for (int w = 0; w < 16; w++) t += s_red[w];
        atomicAdd(&g_acc.seedloss[b], t);
    }
}

// ---------------------------------------------------------------------------
// Scan: remap u-hist -> err-hist (proportional spreading), then suffix scan
// + midpoint Jaccard integration. 1 CTA per (b,k).
// ---------------------------------------------------------------------------
__global__ void __launch_bounds__(1024) scan_kernel(){
    __shared__ float fn[NB];
    __shared__ float warpN[32], warpG[32];
    const int bk = blockIdx.x;
    const int b = bk >> 4;
    const int tid = threadIdx.x, lane = tid & 31, wid = tid >> 5;
    const float G = g_acc.cnt[bk];
    const float KD = (UMAX / (float)NBU) * LOG2E;   // d(i) = exp2(-i*KD)

    for (int i = tid; i < NB; i += 1024) fn[i] = 0.f;
    __syncthreads();

    for (int i = tid; i < NBU; i += 1024){
        unsigned c = g_uhist[bk][i];
        if (!c) continue;
        float phi = (float)NB * exp2f(-(float)i     * KD);
        float plo = (float)NB * exp2f(-(float)(i+1) * KD);
        phi = fminf(phi, (float)NB - 0.001f);
        plo = fminf(plo, phi);
        float span = phi - plo;
        float fc = (float)c;
        int b1 = (int)phi;
        if (span < 1e-6f){
            atomicAdd(&fn[b1], fc);
        } else {
            int b0 = (int)plo;
            float w = fc / span;
            if (b0 == b1){
                atomicAdd(&fn[b0], fc);
            } else {
                atomicAdd(&fn[b0], w * ((float)(b0+1) - plo));
                for (int bb = b0+1; bb < b1; bb++) atomicAdd(&fn[bb], w);
                atomicAdd(&fn[b1], w * (phi - (float)b1));
            }
        }
    }
    __syncthreads();

    const unsigned* __restrict__ hg = g_mhist[bk];
    float lossJ = 0.f, carN = 0.f, carG = 0.f;

    #pragma unroll 1
    for (int c = 0; c < NB/1024; c++){
        int idx = NB - 1 - (c*1024 + tid);
        float n = fn[idx];
        float g = (float)hg[idx];

        float sn = n, sg = g;
        #pragma unroll
        for (int o = 1; o < 32; o <<= 1){
            float tn = __shfl_up_sync(0xffffffffu, sn, o);
            float tg = __shfl_up_sync(0xffffffffu, sg, o);
            if (lane >= o){ sn += tn; sg += tg; }
        }
        if (lane == 31){ warpN[wid] = sn; warpG[wid] = sg; }
        __syncthreads();
        if (wid == 0){
            float wn = warpN[lane], wg = warpG[lane];
            #pragma unroll
            for (int o = 1; o < 32; o <<= 1){
                float tn = __shfl_up_sync(0xffffffffu, wn, o);
                float tg = __shfl_up_sync(0xffffffffu, wg, o);
                if (lane >= o){ wn += tn; wg += tg; }
            }
            warpN[lane] = wn; warpG[lane] = wg;
        }
        __syncthreads();
        float offN = wid ? warpN[wid-1] : 0.f;
        float offG = wid ? warpG[wid-1] : 0.f;
        float totN = warpN[31];
        float totG = warpG[31];
        __syncthreads();

        float cumN = carN + offN + sn;
        float cumG = carG + offG + sg;
        carN += totN;
        carG += totG;

        float nEff = cumN - 0.5f*n;
        float gEff = cumG - 0.5f*g;
        float inter = G - gEff;
        float uni   = G + nEff - gEff;
        lossJ += 1.0f - inter/uni;
    }

    #pragma unroll
    for (int o = 16; o; o >>= 1) lossJ += __shfl_down_sync(0xffffffffu, lossJ, o);
    if (lane == 0) warpN[wid] = lossJ;
    __syncthreads();
    if (tid == 0 && G > 0.f){
        float L = 0.f;
        #pragma unroll
        for (int i = 0; i < 32; i++) L += warpN[i];
        atomicAdd(&g_acc.instloss[b], L * (2.0f/NB));
    }
}

// ---------------------------------------------------------------------------
// Finalize: var loss + presence from raw moments, then combine.
// ---------------------------------------------------------------------------
__global__ void finalize_kernel(float* out){
    __shared__ float s_var[BB], s_pre[BB];
    int t = threadIdx.x;
    if (t < BB){ s_var[t] = 0.f; s_pre[t] = 0.f; }
    __syncthreads();
    if (t < BK){
        float cnt = g_acc.cnt[t];
        if (cnt > 0.f){
            float mean = g_acc.ss[t] / cnt;
            float var = (g_acc.ss2[t] - cnt*mean*mean) / cnt;
            atomicAdd(&s_var[t>>4], var);
            atomicAdd(&s_pre[t>>4], 1.f);
        }
    }
    __syncthreads();
    if (t == 0){
        float tot = 0.f;
        #pragma unroll
        for (int b = 0; b < BB; b++){
            float obj = fmaxf(s_pre[b], 1.0f);
            tot += g_acc.instloss[b] / obj
                 + 10.0f * s_var[b] / obj
                 + g_acc.seedloss[b] / (float)HW;
        }
        out[0] = tot / (float)BB;
    }
}

// ---------------------------------------------------------------------------
extern "C" void kernel_launch(void* const* d_in, const int* in_sizes, int n_in,
                              void* d_out, int out_size) {
    (void)in_sizes; (void)n_in; (void)out_size;
    const float* pred = (const float*)d_in[0];

    void *accp=nullptr, *uhp=nullptr, *mhp=nullptr;
    cudaGetSymbolAddress(&accp, g_acc);
    cudaGetSymbolAddress(&uhp,  g_uhist);
    cudaGetSymbolAddress(&mhp,  g_mhist);
    cudaMemsetAsync(accp, 0, sizeof(Accum), 0);
    cudaMemsetAsync(uhp,  0, sizeof(unsigned)*BK*NBU, 0);
    cudaMemsetAsync(mhp,  0, sizeof(unsigned)*BK*NB, 0);

    detect_kernel<<<1, 32>>>((const unsigned int*)d_in[1]);

    dim3 gp(HW/2048, BB);
    prep_kernel<<<gp, 512>>>(pred, d_in[1], d_in[2]);

    dim3 gm(MSPLIT, BK);
    moments_kernel<<<gm, 512>>>(pred);

    lovasz_hist_kernel<<<BK*SPLIT, 512>>>();

    scan_kernel<<<BK, 1024>>>();

    finalize_kernel<<<1, 128>>>((float*)d_out);
}

// round 5
// speedup vs baseline: 3.6514x; 1.0622x over previous
#include <cuda_runtime.h>
#include <math.h>

#define HH 512
#define WW 512
#define BB 8
#define KK 16
#define HW (HH*WW)
#define BK (BB*KK)
#define NBU 4096                 // u-bins (uniform in s*diff^2)
#define NB  4096                 // err-bins (scan space, err coord = d*4096)
#define UMAX 12.0f
#define SPLIT 4
#define MSPLIT 4
#define INV_GRID (1.0f/1023.0f)
#define LOG2E 1.4426950408889634f

struct Accum {
    float cnt[BK], scol[BK], srow[BK], ss[BK], ss2[BK];
    float seedloss[BB], instloss[BB];
    int is64;
};
__device__ Accum g_acc;
__device__ float2        g_emb[BB*HW];
__device__ float         g_seed[BB*HW];
__device__ unsigned char g_mk[BB*HW];
__device__ unsigned int  g_uhist[BK][NBU];   // nonmask, u-binned
__device__ unsigned int  g_mhist[BK][NB];    // mask, exact err-binned

__device__ __forceinline__ float tanh_fast(float x){
    float y; asm("tanh.approx.f32 %0, %1;" : "=f"(y) : "f"(x)); return y;
}

// ---------------------------------------------------------------------------
__global__ void detect_kernel(const unsigned int* __restrict__ r){
    unsigned any = 0;
    for (int i = threadIdx.x; i < 2048; i += 32) any |= r[2*i + 1];
    unsigned bal = __ballot_sync(0xffffffffu, any != 0u);
    if (threadIdx.x == 0) g_acc.is64 = bal ? 0 : 1;
}

// ---------------------------------------------------------------------------
// Prep: emb = tanh + xy, seed = sigmoid, mask byte, bg seed loss.
// ---------------------------------------------------------------------------
__global__ void __launch_bounds__(512) prep_kernel(const float* __restrict__ pred,
                                                   const void* __restrict__ instp,
                                                   const void* __restrict__ labp) {
    __shared__ float s_bg[16];
    const int tid = threadIdx.x;
    const int b = blockIdx.y;
    const int i4 = blockIdx.x * 2048 + tid * 4;
    const int is64 = g_acc.is64;
    const float* pb = pred + (size_t)b * 4 * HW;
    const size_t off = (size_t)b * HW + i4;

    float4 p0 = *(const float4*)(pb + i4);
    float4 p1 = *(const float4*)(pb + HW + i4);
    float4 p3 = *(const float4*)(pb + 3*HW + i4);

    int inst[4], lab[4];
    if (is64) {
        const int4* ip = (const int4*)instp;
        const int4* lp = (const int4*)labp;
        size_t q = off >> 1;
        int4 a = ip[q],   c = ip[q+1];
        int4 d0 = lp[q],  d1 = lp[q+1];
        inst[0]=a.x; inst[1]=a.z; inst[2]=c.x; inst[3]=c.z;
        lab[0]=d0.x; lab[1]=d0.z; lab[2]=d1.x; lab[3]=d1.z;
    } else {
        int4 a  = ((const int4*)instp)[off>>2];
        int4 d0 = ((const int4*)labp)[off>>2];
        inst[0]=a.x; inst[1]=a.y; inst[2]=a.z; inst[3]=a.w;
        lab[0]=d0.x; lab[1]=d0.y; lab[2]=d0.z; lab[3]=d0.w;
    }

    float y  = (float)(i4 >> 9) * INV_GRID;
    float xb = (float)(i4 & (WW-1)) * INV_GRID;

    const float* p0a = (const float*)&p0;
    const float* p1a = (const float*)&p1;
    const float* p3a = (const float*)&p3;
    float ex[4], ey[4], sd[4];
    #pragma unroll
    for (int j = 0; j < 4; j++) {
        ex[j] = tanh_fast(p0a[j]) + (xb + j*INV_GRID);
        ey[j] = tanh_fast(p1a[j]) + y;
        sd[j] = fmaf(tanh_fast(0.5f*p3a[j]), 0.5f, 0.5f);
    }
    ((float4*)(g_emb+off))[0] = make_float4(ex[0],ey[0],ex[1],ey[1]);
    ((float4*)(g_emb+off))[1] = make_float4(ex[2],ey[2],ex[3],ey[3]);
    *(float4*)(g_seed+off)    = make_float4(sd[0],sd[1],sd[2],sd[3]);

    unsigned mk4 = 0;
    float bg = 0.f;
    #pragma unroll
    for (int j = 0; j < 4; j++) {
        unsigned m = (lab[j]==1 && inst[j]>=1 && inst[j]<=KK) ? (unsigned)inst[j] : 0u;
        mk4 |= m << (8*j);
        if (lab[j]==0) bg += sd[j]*sd[j];
    }
    *(unsigned*)(g_mk+off) = mk4;

    #pragma unroll
    for (int o = 16; o; o >>= 1) bg += __shfl_down_sync(0xffffffffu, bg, o);
    if ((tid & 31) == 0) s_bg[tid>>5] = bg;
    __syncthreads();
    if (tid == 0) {
        float t = 0.f;
        #pragma unroll
        for (int w = 0; w < 16; w++) t += s_bg[w];
        atomicAdd(&g_acc.seedloss[b], t);
    }
}

// ---------------------------------------------------------------------------
// Moments: per (b,k), register accumulation, 16 px/thread skip-fast.
// ---------------------------------------------------------------------------
__global__ void __launch_bounds__(512) moments_kernel(const float* __restrict__ pred){
    __shared__ float s_red[16*5];
    const int bk = blockIdx.y;
    const int b = bk >> 4;
    const unsigned kid4 = ((unsigned)(bk & 15) + 1u) * 0x01010101u;
    const int tid = threadIdx.x;
    const float* p2 = pred + (size_t)b*4*HW + 2*HW;
    const unsigned char* mk = g_mk + (size_t)b*HW;
    const int pbase = blockIdx.x * (HW / MSPLIT);

    float cnt=0.f, scol=0.f, srow=0.f, ss=0.f, ss2=0.f;

    #pragma unroll
    for (int g = 0; g < (HW/MSPLIT)/(512*16); g++){   // 8 iterations
        int i16 = pbase + (g*512 + tid)*16;
        uint4 m = *(const uint4*)(mk + i16);
        unsigned e[4];
        e[0] = __vcmpeq4(m.x, kid4); e[1] = __vcmpeq4(m.y, kid4);
        e[2] = __vcmpeq4(m.z, kid4); e[3] = __vcmpeq4(m.w, kid4);
        if (e[0]|e[1]|e[2]|e[3]){
            float row = (float)(i16 >> 9);
            int colb = i16 & (WW-1);
            #pragma unroll
            for (int q = 0; q < 4; q++){
                if (!e[q]) continue;
                #pragma unroll
                for (int j = 0; j < 4; j++){
                    if ((e[q] >> (8*j)) & 1u){
                        int px = q*4 + j;
                        float v = p2[i16+px];
                        cnt += 1.f; scol += (float)(colb+px); srow += row;
                        ss += v; ss2 = fmaf(v, v, ss2);
                    }
                }
            }
        }
    }
    int lane = tid & 31, wid = tid >> 5;
    #pragma unroll
    for (int o = 16; o; o >>= 1){
        cnt += __shfl_down_sync(0xffffffffu,cnt ,o);
        scol+= __shfl_down_sync(0xffffffffu,scol,o);
        srow+= __shfl_down_sync(0xffffffffu,srow,o);
        ss  += __shfl_down_sync(0xffffffffu,ss  ,o);
        ss2 += __shfl_down_sync(0xffffffffu,ss2 ,o);
    }
    if (lane == 0){
        s_red[wid*5+0]=cnt; s_red[wid*5+1]=scol; s_red[wid*5+2]=srow;
        s_red[wid*5+3]=ss;  s_red[wid*5+4]=ss2;
    }
    __syncthreads();
    if (tid == 0){
        float a0=0,a1=0,a2=0,a3=0,a4=0;
        #pragma unroll
        for (int w=0;w<16;w++){a0+=s_red[w*5];a1+=s_red[w*5+1];a2+=s_red[w*5+2];a3+=s_red[w*5+3];a4+=s_red[w*5+4];}
        if (a0 > 0.f){
            atomicAdd(&g_acc.cnt[bk], a0); atomicAdd(&g_acc.scol[bk], a1);
            atomicAdd(&g_acc.srow[bk], a2); atomicAdd(&g_acc.ss[bk],  a3);
            atomicAdd(&g_acc.ss2[bk],  a4);
        }
    }
}

// ---------------------------------------------------------------------------
// Hist: nonmask -> u-bins via plain smem atomics. Coordinates pre-scaled by
// sqrt(S) so binf = dxs^2 + dys^2 directly. Mask (~3%) -> exact err-bins via
// rare global atomics + seed term, reusing binf for the exp.
// SPLIT=4, grid=512 -> one full wave at 4 CTAs/SM.
// ---------------------------------------------------------------------------
__global__ void __launch_bounds__(512,4) lovasz_hist_kernel(){
    __shared__ unsigned hu[NBU];
    __shared__ float s_red[16];
    const int bs = blockIdx.x;
    const int bk = bs / SPLIT;
    const int part = bs % SPLIT;
    const int b = bk >> 4;
    const int tid = threadIdx.x;

    for (int i = tid; i < NBU; i += 512) hu[i] = 0u;

    const float cntk = g_acc.cnt[bk];
    const float safe = fmaxf(cntk, 1.f);
    const float mean = g_acc.ss[bk] / safe;
    const float cx = (g_acc.scol[bk] / safe) * INV_GRID;
    const float cy = (g_acc.srow[bk] / safe) * INV_GRID;
    const float sE = expf(10.f * mean);
    const float sq  = sqrtf(sE * ((float)NBU / UMAX)); // binf = |e*sq - c*sq|^2
    const float oxs = -cx * sq;
    const float oys = -cy * sq;
    const float KM  = -(UMAX / (float)NBU) * LOG2E;    // d = exp2f(binf*KM)
    const unsigned kid4 = ((unsigned)(bk & 15) + 1u) * 0x01010101u;
    __syncthreads();

    const float2* __restrict__ emb  = g_emb  + (size_t)b*HW;
    const float*  __restrict__ seedp= g_seed + (size_t)b*HW;
    const unsigned char* __restrict__ mk = g_mk + (size_t)b*HW;
    unsigned* __restrict__ mh = g_mhist[bk];
    const int pbase = part * (HW/SPLIT);
    float seedacc = 0.f;

    #pragma unroll 1
    for (int g = 0; g < (HW/SPLIT)/(512*4); g++){   // 32 iterations
        int i4 = pbase + (g*512 + tid)*4;
        float4 e01 = ((const float4*)(emb+i4))[0];
        float4 e23 = ((const float4*)(emb+i4))[1];
        unsigned m4 = *(const unsigned*)(mk + i4);
        unsigned eq = __vcmpeq4(m4, kid4);
        float exs[4] = {e01.x, e01.z, e23.x, e23.z};
        float eys[4] = {e01.y, e01.w, e23.y, e23.w};
        #pragma unroll
        for (int j = 0; j < 4; j++){
            float dxs = fmaf(exs[j], sq, oxs);
            float dys = fmaf(eys[j], sq, oys);
            float binf = fmaf(dxs, dxs, dys*dys);
            if (!((eq >> (8*j)) & 1u)){
                int bin = min((int)binf, NBU-1);
                atomicAdd(&hu[bin], 1u);
            } else {
                float d = exp2f(binf * KM);
                float sv = seedp[i4+j] - d;
                seedacc = fmaf(sv, sv, seedacc);
                int eb = (NB-1) - min(__float2int_rd(d * (float)NB), NB-1);
                atomicAdd(&mh[eb], 1u);
            }
        }
    }
    __syncthreads();
    for (int i = tid; i < NBU; i += 512){
        unsigned n = hu[i]; if (n) atomicAdd(&g_uhist[bk][i], n);
    }
    #pragma unroll
    for (int o = 16; o; o >>= 1) seedacc += __shfl_down_sync(0xffffffffu, seedacc, o);
    if ((tid & 31) == 0) s_red[tid>>5] = seedacc;
    __syncthreads();
    if (tid == 0){
        float t = 0.f;
        #pragma unroll
        for (int w = 0; w < 16; w++) t += s_red[w];
        atomicAdd(&g_acc.seedloss[b], t);
    }
}

// ---------------------------------------------------------------------------
// Scan: remap u-hist -> err-hist (proportional spreading), then suffix scan
// + midpoint Jaccard integration. 1 CTA per (b,k).
// ---------------------------------------------------------------------------
__global__ void __launch_bounds__(1024) scan_kernel(){
    __shared__ float fn[NB];
    __shared__ float warpN[32], warpG[32];
    const int bk = blockIdx.x;
    const int b = bk >> 4;
    const int tid = threadIdx.x, lane = tid & 31, wid = tid >> 5;
    const float G = g_acc.cnt[bk];
    const float KD = (UMAX / (float)NBU) * LOG2E;   // d(i) = exp2(-i*KD)

    for (int i = tid; i < NB; i += 1024) fn[i] = 0.f;
    __syncthreads();

    for (int i = tid; i < NBU; i += 1024){
        unsigned c = g_uhist[bk][i];
        if (!c) continue;
        float phi = (float)NB * exp2f(-(float)i     * KD);
        float plo = (float)NB * exp2f(-(float)(i+1) * KD);
        phi = fminf(phi, (float)NB - 0.001f);
        plo = fminf(plo, phi);
        float span = phi - plo;
        float fc = (float)c;
        int b1 = (int)phi;
        if (span < 1e-6f){
            atomicAdd(&fn[b1], fc);
        } else {
            int b0 = (int)plo;
            float w = fc / span;
            if (b0 == b1){
                atomicAdd(&fn[b0], fc);
            } else {
                atomicAdd(&fn[b0], w * ((float)(b0+1) - plo));
                for (int bb = b0+1; bb < b1; bb++) atomicAdd(&fn[bb], w);
                atomicAdd(&fn[b1], w * (phi - (float)b1));
            }
        }
    }
    __syncthreads();

    const unsigned* __restrict__ hg = g_mhist[bk];
    float lossJ = 0.f, carN = 0.f, carG = 0.f;

    #pragma unroll 1
    for (int c = 0; c < NB/1024; c++){
        int idx = NB - 1 - (c*1024 + tid);
        float n = fn[idx];
        float g = (float)hg[idx];

        float sn = n, sg = g;
        #pragma unroll
        for (int o = 1; o < 32; o <<= 1){
            float tn = __shfl_up_sync(0xffffffffu, sn, o);
            float tg = __shfl_up_sync(0xffffffffu, sg, o);
            if (lane >= o){ sn += tn; sg += tg; }
        }
        if (lane == 31){ warpN[wid] = sn; warpG[wid] = sg; }
        __syncthreads();
        if (wid == 0){
            float wn = warpN[lane], wg = warpG[lane];
            #pragma unroll
            for (int o = 1; o < 32; o <<= 1){
                float tn = __shfl_up_sync(0xffffffffu, wn, o);
                float tg = __shfl_up_sync(0xffffffffu, wg, o);
                if (lane >= o){ wn += tn; wg += tg; }
            }
            warpN[lane] = wn; warpG[lane] = wg;
        }
        __syncthreads();
        float offN = wid ? warpN[wid-1] : 0.f;
        float offG = wid ? warpG[wid-1] : 0.f;
        float totN = warpN[31];
        float totG = warpG[31];
        __syncthreads();

        float cumN = carN + offN + sn;
        float cumG = carG + offG + sg;
        carN += totN;
        carG += totG;

        float nEff = cumN - 0.5f*n;
        float gEff = cumG - 0.5f*g;
        float inter = G - gEff;
        float uni   = G + nEff - gEff;
        lossJ += 1.0f - inter/uni;
    }

    #pragma unroll
    for (int o = 16; o; o >>= 1) lossJ += __shfl_down_sync(0xffffffffu, lossJ, o);
    if (lane == 0) warpN[wid] = lossJ;
    __syncthreads();
    if (tid == 0 && G > 0.f){
        float L = 0.f;
        #pragma unroll
        for (int i = 0; i < 32; i++) L += warpN[i];
        atomicAdd(&g_acc.instloss[b], L * (2.0f/NB));
    }
}

// ---------------------------------------------------------------------------
// Finalize: var loss + presence from raw moments, then combine.
// ---------------------------------------------------------------------------
__global__ void finalize_kernel(float* out){
    __shared__ float s_var[BB], s_pre[BB];
    int t = threadIdx.x;
    if (t < BB){ s_var[t] = 0.f; s_pre[t] = 0.f; }
    __syncthreads();
    if (t < BK){
        float cnt = g_acc.cnt[t];
        if (cnt > 0.f){
            float mean = g_acc.ss[t] / cnt;
            float var = (g_acc.ss2[t] - cnt*mean*mean) / cnt;
            atomicAdd(&s_var[t>>4], var);
            atomicAdd(&s_pre[t>>4], 1.f);
        }
    }
    __syncthreads();
    if (t == 0){
        float tot = 0.f;
        #pragma unroll
        for (int b = 0; b < BB; b++){
            float obj = fmaxf(s_pre[b], 1.0f);
            tot += g_acc.instloss[b] / obj
                 + 10.0f * s_var[b] / obj
                 + g_acc.seedloss[b] / (float)HW;
        }
        out[0] = tot / (float)BB;
    }
}

// ---------------------------------------------------------------------------
extern "C" void kernel_launch(void* const* d_in, const int* in_sizes, int n_in,
                              void* d_out, int out_size) {
    (void)in_sizes; (void)n_in; (void)out_size;
    const float* pred = (const float*)d_in[0];

    void *accp=nullptr, *uhp=nullptr, *mhp=nullptr;
    cudaGetSymbolAddress(&accp, g_acc);
    cudaGetSymbolAddress(&uhp,  g_uhist);
    cudaGetSymbolAddress(&mhp,  g_mhist);
    cudaMemsetAsync(accp, 0, sizeof(Accum), 0);
    cudaMemsetAsync(uhp,  0, sizeof(unsigned)*BK*NBU, 0);
    cudaMemsetAsync(mhp,  0, sizeof(unsigned)*BK*NB, 0);

    detect_kernel<<<1, 32>>>((const unsigned int*)d_in[1]);

    dim3 gp(HW/2048, BB);
    prep_kernel<<<gp, 512>>>(pred, d_in[1], d_in[2]);

    dim3 gm(MSPLIT, BK);
    moments_kernel<<<gm, 512>>>(pred);

    lovasz_hist_kernel<<<BK*SPLIT, 512>>>();

    scan_kernel<<<BK, 1024>>>();

    finalize_kernel<<<1, 128>>>((float*)d_out);
}